// round 4
// baseline (speedup 1.0000x reference)
#include <cuda_runtime.h>
#include <cuda_bf16.h>
#include <cstdint>

// Problem constants
#define BB 2
#define SS 2048
#define DD 1024
#define HH 16
#define DKH 64
#define MM (BB * SS)   // 4096

// ------------------------------------------------------------------
// Scratch (device globals; no allocation allowed)
// ------------------------------------------------------------------
__device__ float g_Q[MM * DD];
__device__ float g_K[MM * DD];
__device__ float g_V[MM * DD];
__device__ float g_O[MM * DD];

// ------------------------------------------------------------------
// Generic 128x128 fp32 GEMM tile:  C[m,n] = sum_k A[m,k] * W[n,k] + bias[n]
// (A row-major [M,K], W row-major [N,K] -> computes A @ W^T + b)
// ------------------------------------------------------------------
#define GM 128
#define GN 128
#define GK 16

__device__ __forceinline__ void gemm128(const float* __restrict__ A,
                                        const float* __restrict__ W,
                                        const float* __restrict__ bias,
                                        float* __restrict__ C,
                                        int K, int N,
                                        float (*As)[GM], float (*Bs)[GN])
{
    const int tid = threadIdx.x;
    const int tx = tid & 15;   // n direction
    const int ty = tid >> 4;   // m direction
    const int m0 = blockIdx.y * GM;
    const int n0 = blockIdx.x * GN;

    float acc[8][8];
#pragma unroll
    for (int i = 0; i < 8; i++)
#pragma unroll
        for (int j = 0; j < 8; j++) acc[i][j] = 0.f;

    for (int kt = 0; kt < K; kt += GK) {
#pragma unroll
        for (int r = 0; r < 2; r++) {
            int p   = tid + r * 256;        // 0..511, each = one float4 of the tile
            int row = p >> 2;               // 0..127
            int c   = (p & 3) << 2;         // 0,4,8,12
            float4 av = *(const float4*)&A[(size_t)(m0 + row) * K + kt + c];
            As[c + 0][row] = av.x; As[c + 1][row] = av.y;
            As[c + 2][row] = av.z; As[c + 3][row] = av.w;
            float4 wv = *(const float4*)&W[(size_t)(n0 + row) * K + kt + c];
            Bs[c + 0][row] = wv.x; Bs[c + 1][row] = wv.y;
            Bs[c + 2][row] = wv.z; Bs[c + 3][row] = wv.w;
        }
        __syncthreads();
#pragma unroll
        for (int k = 0; k < GK; k++) {
            float a[8], b[8];
            *(float4*)&a[0] = *(const float4*)&As[k][ty * 8];
            *(float4*)&a[4] = *(const float4*)&As[k][ty * 8 + 4];
            *(float4*)&b[0] = *(const float4*)&Bs[k][tx * 8];
            *(float4*)&b[4] = *(const float4*)&Bs[k][tx * 8 + 4];
#pragma unroll
            for (int i = 0; i < 8; i++)
#pragma unroll
                for (int j = 0; j < 8; j++)
                    acc[i][j] = fmaf(a[i], b[j], acc[i][j]);
        }
        __syncthreads();
    }

#pragma unroll
    for (int i = 0; i < 8; i++) {
        int m = m0 + ty * 8 + i;
#pragma unroll
        for (int j4 = 0; j4 < 8; j4 += 4) {
            int n = n0 + tx * 8 + j4;
            float4 o;
            o.x = acc[i][j4 + 0] + bias[n + 0];
            o.y = acc[i][j4 + 1] + bias[n + 1];
            o.z = acc[i][j4 + 2] + bias[n + 2];
            o.w = acc[i][j4 + 3] + bias[n + 3];
            *(float4*)&C[(size_t)m * N + n] = o;
        }
    }
}

// ------------------------------------------------------------------
// Kernel 1: fused Q/K/V projections; blockIdx.z selects which.
// ------------------------------------------------------------------
__global__ __launch_bounds__(256, 2)
void proj_kernel(const float* __restrict__ q_in, const float* __restrict__ k_in,
                 const float* __restrict__ v_in,
                 const float* __restrict__ Wq, const float* __restrict__ bq,
                 const float* __restrict__ Wk, const float* __restrict__ bk,
                 const float* __restrict__ Wv, const float* __restrict__ bv)
{
    __shared__ float As[GK][GM];
    __shared__ float Bs[GK][GN];
    const float* A; const float* W; const float* bias; float* C;
    if (blockIdx.z == 0)      { A = q_in; W = Wq; bias = bq; C = g_Q; }
    else if (blockIdx.z == 1) { A = k_in; W = Wk; bias = bk; C = g_K; }
    else                      { A = v_in; W = Wv; bias = bv; C = g_V; }
    gemm128(A, W, bias, C, DD, DD, As, Bs);
}

// ------------------------------------------------------------------
// Kernel 3: output projection from attention scratch.
// ------------------------------------------------------------------
__global__ __launch_bounds__(256, 2)
void out_kernel(const float* __restrict__ Wo, const float* __restrict__ bo,
                float* __restrict__ out)
{
    __shared__ float As[GK][GM];
    __shared__ float Bs[GK][GN];
    gemm128(g_O, Wo, bo, out, DD, DD, As, Bs);
}

// ------------------------------------------------------------------
// Kernel 2: flash attention.
// Grid: (S/64, B*H). Block: 256 threads as 16(tx: key/d cols) x 16(ty: q rows).
// Each thread owns a 4x4 microtile of the 64x64 score block and a 4x4 of O.
// ------------------------------------------------------------------
#define KT_PITCH 68
#define SMEM_QS    (64 * 64)
#define SMEM_KST   (64 * KT_PITCH)
#define SMEM_VS    (64 * 64)
#define SMEM_PS    (64 * 64)
#define ATTN_SMEM_FLOATS (SMEM_QS + SMEM_KST + SMEM_VS + SMEM_PS)
#define ATTN_SMEM_BYTES  (ATTN_SMEM_FLOATS * 4 + 64 * 4)

__global__ __launch_bounds__(256, 3)
void attn_kernel(const int* __restrict__ mask)
{
    extern __shared__ float sm[];
    float* Qs  = sm;                      // [64][64]
    float* KsT = Qs + SMEM_QS;            // [64][KT_PITCH] (d-major, transposed)
    float* Vs  = KsT + SMEM_KST;          // [64][64]
    float* Ps  = Vs + SMEM_VS;            // [64][64]
    int*   msk = (int*)(Ps + SMEM_PS);    // [64]

    const int tid = threadIdx.x;
    const int tx  = tid & 15;             // key col group / d col group
    const int ty  = tid >> 4;             // q row group
    const int q0  = blockIdx.x * 64;
    const int b   = blockIdx.y >> 4;
    const int h   = blockIdx.y & 15;
    const int hoff = h * DKH;

    // Load Q tile once: 64 rows x 64 d
#pragma unroll
    for (int r = 0; r < 4; r++) {
        int idx = tid + r * 256;
        int row = idx >> 4;
        int d4  = (idx & 15) << 2;
        *(float4*)&Qs[row * 64 + d4] =
            *(const float4*)&g_Q[(size_t)((b * SS + q0 + row) * DD) + hoff + d4];
    }

    float m_i[4], l_i[4], O[4][4];
#pragma unroll
    for (int i = 0; i < 4; i++) {
        m_i[i] = -1e30f; l_i[i] = 0.f;
#pragma unroll
        for (int j = 0; j < 4; j++) O[i][j] = 0.f;
    }

    const float scale = 0.125f;  // 1/sqrt(64)

    for (int kb = 0; kb < SS; kb += 64) {
        __syncthreads();  // protect smem reuse from previous iteration's reads

        // Load K (transposed into KsT[d][j]) and V (natural), plus mask
#pragma unroll
        for (int r = 0; r < 4; r++) {
            int idx = tid + r * 256;
            int j   = idx >> 4;
            int d4  = (idx & 15) << 2;
            float4 kv = *(const float4*)&g_K[(size_t)((b * SS + kb + j) * DD) + hoff + d4];
            KsT[(d4 + 0) * KT_PITCH + j] = kv.x;
            KsT[(d4 + 1) * KT_PITCH + j] = kv.y;
            KsT[(d4 + 2) * KT_PITCH + j] = kv.z;
            KsT[(d4 + 3) * KT_PITCH + j] = kv.w;
            float4 vv = *(const float4*)&g_V[(size_t)((b * SS + kb + j) * DD) + hoff + d4];
            *(float4*)&Vs[j * 64 + d4] = vv;
        }
        if (tid < 64) msk[tid] = mask[b * SS + kb + tid];
        __syncthreads();

        // Scores: s[ii][jj] = sum_d Qs[row][d] * KsT[d][col]
        float s[4][4];
#pragma unroll
        for (int i = 0; i < 4; i++)
#pragma unroll
            for (int j = 0; j < 4; j++) s[i][j] = 0.f;

#pragma unroll
        for (int d = 0; d < 64; d++) {
            float bv[4];
            *(float4*)bv = *(const float4*)&KsT[d * KT_PITCH + tx * 4];
#pragma unroll
            for (int ii = 0; ii < 4; ii++) {
                float av = Qs[(ty * 4 + ii) * 64 + d];
#pragma unroll
                for (int jj = 0; jj < 4; jj++)
                    s[ii][jj] = fmaf(av, bv[jj], s[ii][jj]);
            }
        }

        // Scale + mask
#pragma unroll
        for (int ii = 0; ii < 4; ii++)
#pragma unroll
            for (int jj = 0; jj < 4; jj++) {
                float v = s[ii][jj] * scale;
                s[ii][jj] = (msk[tx * 4 + jj] != 0) ? v : -1e30f;
            }

        // Online softmax (row reductions across the 16 tx lanes)
#pragma unroll
        for (int ii = 0; ii < 4; ii++) {
            float rmax = fmaxf(fmaxf(s[ii][0], s[ii][1]), fmaxf(s[ii][2], s[ii][3]));
#pragma unroll
            for (int off = 8; off >= 1; off >>= 1)
                rmax = fmaxf(rmax, __shfl_xor_sync(0xffffffffu, rmax, off));

            float mnew  = fmaxf(m_i[ii], rmax);
            float alpha = __expf(m_i[ii] - mnew);
            m_i[ii] = mnew;

            float rsum = 0.f;
#pragma unroll
            for (int jj = 0; jj < 4; jj++) {
                float p = __expf(s[ii][jj] - mnew);
                s[ii][jj] = p;
                rsum += p;
            }
#pragma unroll
            for (int off = 8; off >= 1; off >>= 1)
                rsum += __shfl_xor_sync(0xffffffffu, rsum, off);

            l_i[ii] = l_i[ii] * alpha + rsum;
#pragma unroll
            for (int jj = 0; jj < 4; jj++) O[ii][jj] *= alpha;

            *(float4*)&Ps[(ty * 4 + ii) * 64 + tx * 4] = *(float4*)&s[ii][0];
        }
        __syncthreads();

        // O += P @ V  (O cols = d dims tx*4..tx*4+3)
#pragma unroll
        for (int j = 0; j < 64; j++) {
            float vv[4];
            *(float4*)vv = *(const float4*)&Vs[j * 64 + tx * 4];
#pragma unroll
            for (int ii = 0; ii < 4; ii++) {
                float p = Ps[(ty * 4 + ii) * 64 + j];
#pragma unroll
                for (int dd = 0; dd < 4; dd++)
                    O[ii][dd] = fmaf(p, vv[dd], O[ii][dd]);
            }
        }
    }

    // Normalize and write to scratch [B*S, D] at head offset
#pragma unroll
    for (int ii = 0; ii < 4; ii++) {
        float inv = 1.0f / l_i[ii];
        float4 o;
        o.x = O[ii][0] * inv; o.y = O[ii][1] * inv;
        o.z = O[ii][2] * inv; o.w = O[ii][3] * inv;
        *(float4*)&g_O[(size_t)((b * SS + q0 + ty * 4 + ii) * DD) + hoff + tx * 4] = o;
    }
}

// ------------------------------------------------------------------
// Launch
// ------------------------------------------------------------------
extern "C" void kernel_launch(void* const* d_in, const int* in_sizes, int n_in,
                              void* d_out, int out_size)
{
    const float* query = (const float*)d_in[0];
    const float* key   = (const float*)d_in[1];
    const float* value = (const float*)d_in[2];
    const int*   mask  = (const int*)  d_in[3];
    const float* Wq    = (const float*)d_in[4];
    const float* bq    = (const float*)d_in[5];
    const float* Wk    = (const float*)d_in[6];
    const float* bk    = (const float*)d_in[7];
    const float* Wv    = (const float*)d_in[8];
    const float* bv    = (const float*)d_in[9];
    const float* Wo    = (const float*)d_in[10];
    const float* bo    = (const float*)d_in[11];
    float* out = (float*)d_out;

    cudaFuncSetAttribute(attn_kernel, cudaFuncAttributeMaxDynamicSharedMemorySize,
                         ATTN_SMEM_BYTES);

    // QKV projections: [4096,1024] @ [1024,1024]^T, z = which projection
    proj_kernel<<<dim3(DD / GN, MM / GM, 3), 256>>>(query, key, value,
                                                    Wq, bq, Wk, bk, Wv, bv);
    // Flash attention: (S/64 q-blocks, B*H)
    attn_kernel<<<dim3(SS / 64, BB * HH), 256, ATTN_SMEM_BYTES>>>(mask);
    // Output projection
    out_kernel<<<dim3(DD / GN, MM / GM), 256>>>(Wo, bo, out);
}

// round 9
// speedup vs baseline: 1.4878x; 1.4878x over previous
#include <cuda_runtime.h>
#include <cuda_bf16.h>
#include <cstdint>

// Problem constants
#define BB 2
#define SS 2048
#define DD 1024
#define HH 16
#define DKH 64
#define MM (BB * SS)   // 4096

// ------------------------------------------------------------------
// Scratch (device globals; no allocation allowed)
// ------------------------------------------------------------------
__device__ __align__(16) float g_Q[MM * DD];
__device__ __align__(16) float g_K[MM * DD];
__device__ __align__(16) float g_V[MM * DD];
__device__ __align__(16) float g_O[MM * DD];

// ------------------------------------------------------------------
// tf32 helpers
// ------------------------------------------------------------------
__device__ __forceinline__ uint32_t f2tf(float x) {
    uint32_t r;
    asm("cvt.rna.tf32.f32 %0, %1;" : "=r"(r) : "f"(x));
    return r;
}

__device__ __forceinline__ void mma_tf32(float* c, uint32_t a0, uint32_t a1,
                                         uint32_t a2, uint32_t a3,
                                         uint32_t b0, uint32_t b1) {
    asm volatile(
        "mma.sync.aligned.m16n8k8.row.col.f32.tf32.tf32.f32 "
        "{%0,%1,%2,%3}, {%4,%5,%6,%7}, {%8,%9}, {%0,%1,%2,%3};"
        : "+f"(c[0]), "+f"(c[1]), "+f"(c[2]), "+f"(c[3])
        : "r"(a0), "r"(a1), "r"(a2), "r"(a3), "r"(b0), "r"(b1));
}

// ==================================================================
// Warp-level tf32 tensor-core GEMM: C[m,n] = sum_k A[m,k]*W[n,k] + bias[n]
// Block tile 128x128, K chunk 32. 8 warps in 4(m) x 2(n); each warp 32x64.
// Per warp: 2(m) x 8(n) m16n8k8 fragments. No TMEM / mbarriers — hang-proof.
// ==================================================================
#define SPITCH 36   // smem row pitch in 32-bit words (bank-conflict-free frags)

__device__ __forceinline__ void gemm_mma(const float* __restrict__ A,
                                         const float* __restrict__ W,
                                         const float* __restrict__ bias,
                                         float* __restrict__ C,
                                         uint32_t* As, uint32_t* Bs)
{
    const int tid = threadIdx.x;
    const int wid = tid >> 5;
    const int lid = tid & 31;
    const int g   = lid >> 2;   // group id (row within fragment)
    const int t   = lid & 3;    // thread-in-group (col within fragment)
    const int wm  = (wid >> 1) * 32;   // warp m offset in tile
    const int wn  = (wid & 1) * 64;    // warp n offset in tile
    const int m0  = blockIdx.y * 128;
    const int n0  = blockIdx.x * 128;

    float acc[2][8][4];
#pragma unroll
    for (int i = 0; i < 2; i++)
#pragma unroll
        for (int j = 0; j < 8; j++)
#pragma unroll
            for (int r = 0; r < 4; r++) acc[i][j][r] = 0.f;

    for (int kt = 0; kt < DD; kt += 32) {
        __syncthreads();   // protect smem from previous iteration's readers
        // Load + convert A tile [128][32] and B tile (=W) [128][32]
#pragma unroll
        for (int i = 0; i < 4; i++) {
            int idx = tid + i * 256;          // 0..1023
            int row = idx >> 3;               // 0..127
            int col = (idx & 7) * 4;          // 0,4,...,28
            float4 av = *(const float4*)&A[(size_t)(m0 + row) * DD + kt + col];
            uint4 au = make_uint4(f2tf(av.x), f2tf(av.y), f2tf(av.z), f2tf(av.w));
            *(uint4*)&As[row * SPITCH + col] = au;
            float4 wv = *(const float4*)&W[(size_t)(n0 + row) * DD + kt + col];
            uint4 wu = make_uint4(f2tf(wv.x), f2tf(wv.y), f2tf(wv.z), f2tf(wv.w));
            *(uint4*)&Bs[row * SPITCH + col] = wu;
        }
        __syncthreads();

#pragma unroll
        for (int k8 = 0; k8 < 4; k8++) {
            const int kc = k8 * 8;
            // A fragments for 2 m-tiles
            uint32_t a[2][4];
#pragma unroll
            for (int mt = 0; mt < 2; mt++) {
                const int ar = wm + mt * 16 + g;
                a[mt][0] = As[ar * SPITCH + kc + t];
                a[mt][1] = As[(ar + 8) * SPITCH + kc + t];
                a[mt][2] = As[ar * SPITCH + kc + t + 4];
                a[mt][3] = As[(ar + 8) * SPITCH + kc + t + 4];
            }
            // B fragments for 8 n-tiles
            uint32_t b[8][2];
#pragma unroll
            for (int nt = 0; nt < 8; nt++) {
                const int br = wn + nt * 8 + g;
                b[nt][0] = Bs[br * SPITCH + kc + t];
                b[nt][1] = Bs[br * SPITCH + kc + t + 4];
            }
#pragma unroll
            for (int mt = 0; mt < 2; mt++)
#pragma unroll
                for (int nt = 0; nt < 8; nt++)
                    mma_tf32(acc[mt][nt], a[mt][0], a[mt][1], a[mt][2], a[mt][3],
                             b[nt][0], b[nt][1]);
        }
    }

    // Epilogue: c0/c1 -> (row g, cols 2t,2t+1); c2/c3 -> (row g+8)
#pragma unroll
    for (int mt = 0; mt < 2; mt++) {
        const int mrow0 = m0 + wm + mt * 16 + g;
#pragma unroll
        for (int nt = 0; nt < 8; nt++) {
            const int n = n0 + wn + nt * 8 + 2 * t;
            const float bx = bias[n], by = bias[n + 1];
            float2 lo = make_float2(acc[mt][nt][0] + bx, acc[mt][nt][1] + by);
            float2 hi = make_float2(acc[mt][nt][2] + bx, acc[mt][nt][3] + by);
            *(float2*)&C[(size_t)mrow0 * DD + n] = lo;
            *(float2*)&C[(size_t)(mrow0 + 8) * DD + n] = hi;
        }
    }
}

// ------------------------------------------------------------------
// Kernel 1: fused Q/K/V projections; blockIdx.z selects which.
// ------------------------------------------------------------------
__global__ __launch_bounds__(256, 2)
void proj_kernel(const float* __restrict__ q_in, const float* __restrict__ k_in,
                 const float* __restrict__ v_in,
                 const float* __restrict__ Wq, const float* __restrict__ bq,
                 const float* __restrict__ Wk, const float* __restrict__ bk,
                 const float* __restrict__ Wv, const float* __restrict__ bv)
{
    __shared__ uint32_t As[128 * SPITCH];
    __shared__ uint32_t Bs[128 * SPITCH];
    const float* A; const float* W; const float* bias; float* C;
    if (blockIdx.z == 0)      { A = q_in; W = Wq; bias = bq; C = g_Q; }
    else if (blockIdx.z == 1) { A = k_in; W = Wk; bias = bk; C = g_K; }
    else                      { A = v_in; W = Wv; bias = bv; C = g_V; }
    gemm_mma(A, W, bias, C, As, Bs);
}

// ------------------------------------------------------------------
// Kernel 3: output projection.
// ------------------------------------------------------------------
__global__ __launch_bounds__(256, 2)
void out_kernel(const float* __restrict__ Wo, const float* __restrict__ bo,
                float* __restrict__ out)
{
    __shared__ uint32_t As[128 * SPITCH];
    __shared__ uint32_t Bs[128 * SPITCH];
    gemm_mma(g_O, Wo, bo, out, As, Bs);
}

// ------------------------------------------------------------------
// Kernel 2: flash attention (fp32 SIMT — unchanged from passing R3).
// ------------------------------------------------------------------
#define KT_PITCH 68
#define SMEM_QS    (64 * 64)
#define SMEM_KST   (64 * KT_PITCH)
#define SMEM_VS    (64 * 64)
#define SMEM_PS    (64 * 64)
#define ATTN_SMEM_FLOATS (SMEM_QS + SMEM_KST + SMEM_VS + SMEM_PS)
#define ATTN_SMEM_BYTES  (ATTN_SMEM_FLOATS * 4 + 64 * 4)

__global__ __launch_bounds__(256, 3)
void attn_kernel(const int* __restrict__ mask)
{
    extern __shared__ float sm[];
    float* Qs  = sm;
    float* KsT = Qs + SMEM_QS;
    float* Vs  = KsT + SMEM_KST;
    float* Ps  = Vs + SMEM_VS;
    int*   msk = (int*)(Ps + SMEM_PS);

    const int tid = threadIdx.x;
    const int tx  = tid & 15;
    const int ty  = tid >> 4;
    const int q0  = blockIdx.x * 64;
    const int b   = blockIdx.y >> 4;
    const int h   = blockIdx.y & 15;
    const int hoff = h * DKH;

#pragma unroll
    for (int r = 0; r < 4; r++) {
        int idx = tid + r * 256;
        int row = idx >> 4;
        int d4  = (idx & 15) << 2;
        *(float4*)&Qs[row * 64 + d4] =
            *(const float4*)&g_Q[(size_t)((b * SS + q0 + row) * DD) + hoff + d4];
    }

    float m_i[4], l_i[4], O[4][4];
#pragma unroll
    for (int i = 0; i < 4; i++) {
        m_i[i] = -1e30f; l_i[i] = 0.f;
#pragma unroll
        for (int j = 0; j < 4; j++) O[i][j] = 0.f;
    }

    const float scale = 0.125f;

    for (int kb = 0; kb < SS; kb += 64) {
        __syncthreads();

#pragma unroll
        for (int r = 0; r < 4; r++) {
            int idx = tid + r * 256;
            int j   = idx >> 4;
            int d4  = (idx & 15) << 2;
            float4 kv = *(const float4*)&g_K[(size_t)((b * SS + kb + j) * DD) + hoff + d4];
            KsT[(d4 + 0) * KT_PITCH + j] = kv.x;
            KsT[(d4 + 1) * KT_PITCH + j] = kv.y;
            KsT[(d4 + 2) * KT_PITCH + j] = kv.z;
            KsT[(d4 + 3) * KT_PITCH + j] = kv.w;
            float4 vv = *(const float4*)&g_V[(size_t)((b * SS + kb + j) * DD) + hoff + d4];
            *(float4*)&Vs[j * 64 + d4] = vv;
        }
        if (tid < 64) msk[tid] = mask[b * SS + kb + tid];
        __syncthreads();

        float s[4][4];
#pragma unroll
        for (int i = 0; i < 4; i++)
#pragma unroll
            for (int j = 0; j < 4; j++) s[i][j] = 0.f;

#pragma unroll
        for (int d = 0; d < 64; d++) {
            float bv[4];
            *(float4*)bv = *(const float4*)&KsT[d * KT_PITCH + tx * 4];
#pragma unroll
            for (int ii = 0; ii < 4; ii++) {
                float av = Qs[(ty * 4 + ii) * 64 + d];
#pragma unroll
                for (int jj = 0; jj < 4; jj++)
                    s[ii][jj] = fmaf(av, bv[jj], s[ii][jj]);
            }
        }

#pragma unroll
        for (int ii = 0; ii < 4; ii++)
#pragma unroll
            for (int jj = 0; jj < 4; jj++) {
                float v = s[ii][jj] * scale;
                s[ii][jj] = (msk[tx * 4 + jj] != 0) ? v : -1e30f;
            }

#pragma unroll
        for (int ii = 0; ii < 4; ii++) {
            float rmax = fmaxf(fmaxf(s[ii][0], s[ii][1]), fmaxf(s[ii][2], s[ii][3]));
#pragma unroll
            for (int off = 8; off >= 1; off >>= 1)
                rmax = fmaxf(rmax, __shfl_xor_sync(0xffffffffu, rmax, off));

            float mnew  = fmaxf(m_i[ii], rmax);
            float alpha = __expf(m_i[ii] - mnew);
            m_i[ii] = mnew;

            float rsum = 0.f;
#pragma unroll
            for (int jj = 0; jj < 4; jj++) {
                float p = __expf(s[ii][jj] - mnew);
                s[ii][jj] = p;
                rsum += p;
            }
#pragma unroll
            for (int off = 8; off >= 1; off >>= 1)
                rsum += __shfl_xor_sync(0xffffffffu, rsum, off);

            l_i[ii] = l_i[ii] * alpha + rsum;
#pragma unroll
            for (int jj = 0; jj < 4; jj++) O[ii][jj] *= alpha;

            *(float4*)&Ps[(ty * 4 + ii) * 64 + tx * 4] = *(float4*)&s[ii][0];
        }
        __syncthreads();

#pragma unroll
        for (int j = 0; j < 64; j++) {
            float vv[4];
            *(float4*)vv = *(const float4*)&Vs[j * 64 + tx * 4];
#pragma unroll
            for (int ii = 0; ii < 4; ii++) {
                float p = Ps[(ty * 4 + ii) * 64 + j];
#pragma unroll
                for (int dd = 0; dd < 4; dd++)
                    O[ii][dd] = fmaf(p, vv[dd], O[ii][dd]);
            }
        }
    }

#pragma unroll
    for (int ii = 0; ii < 4; ii++) {
        float inv = 1.0f / l_i[ii];
        float4 o;
        o.x = O[ii][0] * inv; o.y = O[ii][1] * inv;
        o.z = O[ii][2] * inv; o.w = O[ii][3] * inv;
        *(float4*)&g_O[(size_t)((b * SS + q0 + ty * 4 + ii) * DD) + hoff + tx * 4] = o;
    }
}

// ------------------------------------------------------------------
// Launch
// ------------------------------------------------------------------
extern "C" void kernel_launch(void* const* d_in, const int* in_sizes, int n_in,
                              void* d_out, int out_size)
{
    const float* query = (const float*)d_in[0];
    const float* key   = (const float*)d_in[1];
    const float* value = (const float*)d_in[2];
    const int*   mask  = (const int*)  d_in[3];
    const float* Wq    = (const float*)d_in[4];
    const float* bq    = (const float*)d_in[5];
    const float* Wk    = (const float*)d_in[6];
    const float* bk    = (const float*)d_in[7];
    const float* Wv    = (const float*)d_in[8];
    const float* bv    = (const float*)d_in[9];
    const float* Wo    = (const float*)d_in[10];
    const float* bo    = (const float*)d_in[11];
    float* out = (float*)d_out;

    cudaFuncSetAttribute(attn_kernel, cudaFuncAttributeMaxDynamicSharedMemorySize,
                         ATTN_SMEM_BYTES);

    // QKV projections: [4096,1024] @ [1024,1024]^T, z = which projection
    proj_kernel<<<dim3(DD / 128, MM / 128, 3), 256>>>(query, key, value,
                                                      Wq, bq, Wk, bk, Wv, bv);
    // Flash attention: (S/64 q-blocks, B*H)
    attn_kernel<<<dim3(SS / 64, BB * HH), 256, ATTN_SMEM_BYTES>>>(mask);
    // Output projection
    out_kernel<<<dim3(DD / 128, MM / 128), 256>>>(Wo, bo, out);
}

// round 11
// speedup vs baseline: 2.7928x; 1.8772x over previous
#include <cuda_runtime.h>
#include <cuda_bf16.h>
#include <cstdint>

// Problem constants
#define BB 2
#define SS 2048
#define DD 1024
#define HH 16
#define DKH 64
#define MM (BB * SS)   // 4096

// ------------------------------------------------------------------
// Scratch (device globals; no allocation allowed)
// ------------------------------------------------------------------
__device__ __align__(16) float g_Q[MM * DD];
__device__ __align__(16) float g_K[MM * DD];
__device__ __align__(16) float g_V[MM * DD];
__device__ __align__(16) float g_O[MM * DD];

// ------------------------------------------------------------------
// tf32 helpers
// ------------------------------------------------------------------
__device__ __forceinline__ uint32_t f2tf(float x) {
    uint32_t r;
    asm("cvt.rna.tf32.f32 %0, %1;" : "=r"(r) : "f"(x));
    return r;
}

__device__ __forceinline__ void mma_tf32(float* c, uint32_t a0, uint32_t a1,
                                         uint32_t a2, uint32_t a3,
                                         uint32_t b0, uint32_t b1) {
    asm volatile(
        "mma.sync.aligned.m16n8k8.row.col.f32.tf32.tf32.f32 "
        "{%0,%1,%2,%3}, {%4,%5,%6,%7}, {%8,%9}, {%0,%1,%2,%3};"
        : "+f"(c[0]), "+f"(c[1]), "+f"(c[2]), "+f"(c[3])
        : "r"(a0), "r"(a1), "r"(a2), "r"(a3), "r"(b0), "r"(b1));
}

// ==================================================================
// Warp-level tf32 tensor-core GEMM: C[m,n] = sum_k A[m,k]*W[n,k] + bias[n]
// Block tile 128x128, K chunk 32. 8 warps in 4(m) x 2(n); each warp 32x64.
// ==================================================================
#define SPITCH 36   // smem row pitch in 32-bit words (bank-conflict-free frags)

__device__ __forceinline__ void gemm_mma(const float* __restrict__ A,
                                         const float* __restrict__ W,
                                         const float* __restrict__ bias,
                                         float* __restrict__ C,
                                         uint32_t* As, uint32_t* Bs)
{
    const int tid = threadIdx.x;
    const int wid = tid >> 5;
    const int lid = tid & 31;
    const int g   = lid >> 2;
    const int t   = lid & 3;
    const int wm  = (wid >> 1) * 32;
    const int wn  = (wid & 1) * 64;
    const int m0  = blockIdx.y * 128;
    const int n0  = blockIdx.x * 128;

    float acc[2][8][4];
#pragma unroll
    for (int i = 0; i < 2; i++)
#pragma unroll
        for (int j = 0; j < 8; j++)
#pragma unroll
            for (int r = 0; r < 4; r++) acc[i][j][r] = 0.f;

    for (int kt = 0; kt < DD; kt += 32) {
        __syncthreads();
#pragma unroll
        for (int i = 0; i < 4; i++) {
            int idx = tid + i * 256;
            int row = idx >> 3;
            int col = (idx & 7) * 4;
            float4 av = *(const float4*)&A[(size_t)(m0 + row) * DD + kt + col];
            uint4 au = make_uint4(f2tf(av.x), f2tf(av.y), f2tf(av.z), f2tf(av.w));
            *(uint4*)&As[row * SPITCH + col] = au;
            float4 wv = *(const float4*)&W[(size_t)(n0 + row) * DD + kt + col];
            uint4 wu = make_uint4(f2tf(wv.x), f2tf(wv.y), f2tf(wv.z), f2tf(wv.w));
            *(uint4*)&Bs[row * SPITCH + col] = wu;
        }
        __syncthreads();

#pragma unroll
        for (int k8 = 0; k8 < 4; k8++) {
            const int kc = k8 * 8;
            uint32_t a[2][4];
#pragma unroll
            for (int mt = 0; mt < 2; mt++) {
                const int ar = wm + mt * 16 + g;
                a[mt][0] = As[ar * SPITCH + kc + t];
                a[mt][1] = As[(ar + 8) * SPITCH + kc + t];
                a[mt][2] = As[ar * SPITCH + kc + t + 4];
                a[mt][3] = As[(ar + 8) * SPITCH + kc + t + 4];
            }
            uint32_t b[8][2];
#pragma unroll
            for (int nt = 0; nt < 8; nt++) {
                const int br = wn + nt * 8 + g;
                b[nt][0] = Bs[br * SPITCH + kc + t];
                b[nt][1] = Bs[br * SPITCH + kc + t + 4];
            }
#pragma unroll
            for (int mt = 0; mt < 2; mt++)
#pragma unroll
                for (int nt = 0; nt < 8; nt++)
                    mma_tf32(acc[mt][nt], a[mt][0], a[mt][1], a[mt][2], a[mt][3],
                             b[nt][0], b[nt][1]);
        }
    }

#pragma unroll
    for (int mt = 0; mt < 2; mt++) {
        const int mrow0 = m0 + wm + mt * 16 + g;
#pragma unroll
        for (int nt = 0; nt < 8; nt++) {
            const int n = n0 + wn + nt * 8 + 2 * t;
            const float bx = bias[n], by = bias[n + 1];
            float2 lo = make_float2(acc[mt][nt][0] + bx, acc[mt][nt][1] + by);
            float2 hi = make_float2(acc[mt][nt][2] + bx, acc[mt][nt][3] + by);
            *(float2*)&C[(size_t)mrow0 * DD + n] = lo;
            *(float2*)&C[(size_t)(mrow0 + 8) * DD + n] = hi;
        }
    }
}

__global__ __launch_bounds__(256, 2)
void proj_kernel(const float* __restrict__ q_in, const float* __restrict__ k_in,
                 const float* __restrict__ v_in,
                 const float* __restrict__ Wq, const float* __restrict__ bq,
                 const float* __restrict__ Wk, const float* __restrict__ bk,
                 const float* __restrict__ Wv, const float* __restrict__ bv)
{
    __shared__ uint32_t As[128 * SPITCH];
    __shared__ uint32_t Bs[128 * SPITCH];
    const float* A; const float* W; const float* bias; float* C;
    if (blockIdx.z == 0)      { A = q_in; W = Wq; bias = bq; C = g_Q; }
    else if (blockIdx.z == 1) { A = k_in; W = Wk; bias = bk; C = g_K; }
    else                      { A = v_in; W = Wv; bias = bv; C = g_V; }
    gemm_mma(A, W, bias, C, As, Bs);
}

__global__ __launch_bounds__(256, 2)
void out_kernel(const float* __restrict__ Wo, const float* __restrict__ bo,
                float* __restrict__ out)
{
    __shared__ uint32_t As[128 * SPITCH];
    __shared__ uint32_t Bs[128 * SPITCH];
    gemm_mma(g_O, Wo, bo, out, As, Bs);
}

// ==================================================================
// Tensor-core flash attention.
// Grid: (S/128, B*H). 256 threads = 8 warps; warp w owns q-rows w*16..w*16+15.
// Key tile 64. All MMAs are mma.sync m16n8k8 tf32 (register fragments).
// ==================================================================
#define AQT 128
#define AKT 64
#define AP  68    // smem pitch in words

// smem word offsets
#define AOFF_QS   0
#define AOFF_KS   (AQT * AP)                 // 8704
#define AOFF_VST  (AOFF_KS + AKT * AP)       // 13056
#define AOFF_PS   (AOFF_VST + 64 * AP)       // 17408
#define AOFF_MSK  (AOFF_PS + AQT * AP)       // 26112
#define ATTN_SMEM_BYTES ((AOFF_MSK + AKT) * 4)   // 104704

__global__ __launch_bounds__(256, 2)
void attn_tc_kernel(const int* __restrict__ mask)
{
    extern __shared__ uint32_t smw[];
    uint32_t* Qs  = smw + AOFF_QS;   // [128 q][64 d]   tf32
    uint32_t* Ks  = smw + AOFF_KS;   // [64 key][64 d]  tf32
    uint32_t* VsT = smw + AOFF_VST;  // [64 d][64 key]  tf32 (transposed)
    uint32_t* Ps  = smw + AOFF_PS;   // [128 q][64 key] tf32
    int*      msk = (int*)(smw + AOFF_MSK);

    const int tid = threadIdx.x;
    const int wid = tid >> 5, lid = tid & 31;
    const int g = lid >> 2, t = lid & 3;
    const int wq = wid * 16;            // warp's q-row base within tile
    const int q0 = blockIdx.x * AQT;
    const int b  = blockIdx.y >> 4;
    const int h  = blockIdx.y & 15;
    const int hoff = h * DKH;
    const float* Qg = g_Q + (size_t)(b * SS) * DD + hoff;
    const float* Kg = g_K + (size_t)(b * SS) * DD + hoff;
    const float* Vg = g_V + (size_t)(b * SS) * DD + hoff;

    // Stage Q tile (tf32) once: 128 x 64 = 2048 float4 / 256 thr = 8 each
#pragma unroll
    for (int i = 0; i < 8; i++) {
        int idx = tid + i * 256;
        int row = idx >> 4;
        int c4  = (idx & 15) * 4;
        float4 v = *(const float4*)&Qg[(size_t)(q0 + row) * DD + c4];
        uint4 u = make_uint4(f2tf(v.x), f2tf(v.y), f2tf(v.z), f2tf(v.w));
        *(uint4*)&Qs[row * AP + c4] = u;
    }

    float m0 = -1e30f, m1 = -1e30f, l0 = 0.f, l1 = 0.f;
    float o[8][4];
#pragma unroll
    for (int nt = 0; nt < 8; nt++)
#pragma unroll
        for (int r = 0; r < 4; r++) o[nt][r] = 0.f;

    const float scale = 0.125f;  // 1/sqrt(64)

    for (int kb = 0; kb < SS; kb += AKT) {
        __syncthreads();   // prev iter's Ks/VsT/Ps reads done (mma.sync is synchronous)

        // Load K tile [64][64] (key-major) and V transposed [d][key]
#pragma unroll
        for (int i = 0; i < 4; i++) {
            int idx = tid + i * 256;
            int row = idx >> 4;        // key 0..63
            int c4  = (idx & 15) * 4;  // d 0..60
            float4 kv = *(const float4*)&Kg[(size_t)(kb + row) * DD + c4];
            uint4 ku = make_uint4(f2tf(kv.x), f2tf(kv.y), f2tf(kv.z), f2tf(kv.w));
            *(uint4*)&Ks[row * AP + c4] = ku;
            float4 vv = *(const float4*)&Vg[(size_t)(kb + row) * DD + c4];
            VsT[(c4 + 0) * AP + row] = f2tf(vv.x);
            VsT[(c4 + 1) * AP + row] = f2tf(vv.y);
            VsT[(c4 + 2) * AP + row] = f2tf(vv.z);
            VsT[(c4 + 3) * AP + row] = f2tf(vv.w);
        }
        if (tid < AKT) msk[tid] = mask[b * SS + kb + tid];
        __syncthreads();

        // ---- Scores: S = Q @ K^T (rows wq+g / wq+g+8, cols = 64 keys) ----
        float s[8][4];
#pragma unroll
        for (int nt = 0; nt < 8; nt++)
#pragma unroll
            for (int r = 0; r < 4; r++) s[nt][r] = 0.f;

#pragma unroll
        for (int kc = 0; kc < 8; kc++) {
            const int kk = kc * 8;
            uint32_t qa0 = Qs[(wq + g) * AP + kk + t];
            uint32_t qa1 = Qs[(wq + g + 8) * AP + kk + t];
            uint32_t qa2 = Qs[(wq + g) * AP + kk + t + 4];
            uint32_t qa3 = Qs[(wq + g + 8) * AP + kk + t + 4];
#pragma unroll
            for (int nt = 0; nt < 8; nt++) {
                uint32_t b0 = Ks[(nt * 8 + g) * AP + kk + t];
                uint32_t b1 = Ks[(nt * 8 + g) * AP + kk + t + 4];
                mma_tf32(s[nt], qa0, qa1, qa2, qa3, b0, b1);
            }
        }

        // ---- Scale + mask ----
#pragma unroll
        for (int nt = 0; nt < 8; nt++) {
            const int c0 = nt * 8 + 2 * t;
            const int mk0 = msk[c0], mk1 = msk[c0 + 1];
            s[nt][0] = mk0 ? s[nt][0] * scale : -1e30f;
            s[nt][1] = mk1 ? s[nt][1] * scale : -1e30f;
            s[nt][2] = mk0 ? s[nt][2] * scale : -1e30f;
            s[nt][3] = mk1 ? s[nt][3] * scale : -1e30f;
        }

        // ---- Online softmax (rows g and g+8; reduce over quad lanes t) ----
        float mx0 = -1e30f, mx1 = -1e30f;
#pragma unroll
        for (int nt = 0; nt < 8; nt++) {
            mx0 = fmaxf(mx0, fmaxf(s[nt][0], s[nt][1]));
            mx1 = fmaxf(mx1, fmaxf(s[nt][2], s[nt][3]));
        }
#pragma unroll
        for (int off = 1; off <= 2; off <<= 1) {
            mx0 = fmaxf(mx0, __shfl_xor_sync(0xffffffffu, mx0, off));
            mx1 = fmaxf(mx1, __shfl_xor_sync(0xffffffffu, mx1, off));
        }
        float mn0 = fmaxf(m0, mx0), mn1 = fmaxf(m1, mx1);
        float al0 = __expf(m0 - mn0), al1 = __expf(m1 - mn1);
        m0 = mn0; m1 = mn1;

        float sm0 = 0.f, sm1 = 0.f;
#pragma unroll
        for (int nt = 0; nt < 8; nt++) {
            s[nt][0] = __expf(s[nt][0] - mn0);
            s[nt][1] = __expf(s[nt][1] - mn0);
            s[nt][2] = __expf(s[nt][2] - mn1);
            s[nt][3] = __expf(s[nt][3] - mn1);
            sm0 += s[nt][0] + s[nt][1];
            sm1 += s[nt][2] + s[nt][3];
        }
#pragma unroll
        for (int off = 1; off <= 2; off <<= 1) {
            sm0 += __shfl_xor_sync(0xffffffffu, sm0, off);
            sm1 += __shfl_xor_sync(0xffffffffu, sm1, off);
        }
        l0 = l0 * al0 + sm0;
        l1 = l1 * al1 + sm1;
#pragma unroll
        for (int nt = 0; nt < 8; nt++) {
            o[nt][0] *= al0; o[nt][1] *= al0;
            o[nt][2] *= al1; o[nt][3] *= al1;
        }

        // ---- Write P (tf32) to smem ----
#pragma unroll
        for (int nt = 0; nt < 8; nt++) {
            const int c0 = nt * 8 + 2 * t;
            uint2 lo = make_uint2(f2tf(s[nt][0]), f2tf(s[nt][1]));
            uint2 hi = make_uint2(f2tf(s[nt][2]), f2tf(s[nt][3]));
            *(uint2*)&Ps[(wq + g) * AP + c0] = lo;
            *(uint2*)&Ps[(wq + g + 8) * AP + c0] = hi;
        }
        __syncthreads();

        // ---- O += P @ V  (n = 64 d-cols, k = 64 keys) ----
#pragma unroll
        for (int kc = 0; kc < 8; kc++) {
            const int kk = kc * 8;
            uint32_t a0 = Ps[(wq + g) * AP + kk + t];
            uint32_t a1 = Ps[(wq + g + 8) * AP + kk + t];
            uint32_t a2 = Ps[(wq + g) * AP + kk + t + 4];
            uint32_t a3 = Ps[(wq + g + 8) * AP + kk + t + 4];
#pragma unroll
            for (int nt = 0; nt < 8; nt++) {
                uint32_t b0 = VsT[(nt * 8 + g) * AP + kk + t];
                uint32_t b1 = VsT[(nt * 8 + g) * AP + kk + t + 4];
                mma_tf32(o[nt], a0, a1, a2, a3, b0, b1);
            }
        }
    }

    // ---- Normalize + write O tile ----
    const float inv0 = 1.0f / l0, inv1 = 1.0f / l1;
    float* Og = g_O + (size_t)(b * SS) * DD + hoff;
#pragma unroll
    for (int nt = 0; nt < 8; nt++) {
        const int d = nt * 8 + 2 * t;
        float2 lo = make_float2(o[nt][0] * inv0, o[nt][1] * inv0);
        float2 hi = make_float2(o[nt][2] * inv1, o[nt][3] * inv1);
        *(float2*)&Og[(size_t)(q0 + wq + g) * DD + d] = lo;
        *(float2*)&Og[(size_t)(q0 + wq + g + 8) * DD + d] = hi;
    }
}

// ------------------------------------------------------------------
// Launch
// ------------------------------------------------------------------
extern "C" void kernel_launch(void* const* d_in, const int* in_sizes, int n_in,
                              void* d_out, int out_size)
{
    const float* query = (const float*)d_in[0];
    const float* key   = (const float*)d_in[1];
    const float* value = (const float*)d_in[2];
    const int*   mask  = (const int*)  d_in[3];
    const float* Wq    = (const float*)d_in[4];
    const float* bq    = (const float*)d_in[5];
    const float* Wk    = (const float*)d_in[6];
    const float* bk    = (const float*)d_in[7];
    const float* Wv    = (const float*)d_in[8];
    const float* bv    = (const float*)d_in[9];
    const float* Wo    = (const float*)d_in[10];
    const float* bo    = (const float*)d_in[11];
    float* out = (float*)d_out;

    cudaFuncSetAttribute(attn_tc_kernel, cudaFuncAttributeMaxDynamicSharedMemorySize,
                         ATTN_SMEM_BYTES);

    // QKV projections
    proj_kernel<<<dim3(DD / 128, MM / 128, 3), 256>>>(query, key, value,
                                                      Wq, bq, Wk, bk, Wv, bv);
    // Tensor-core flash attention: (S/128 q-tiles, B*H)
    attn_tc_kernel<<<dim3(SS / AQT, BB * HH), 256, ATTN_SMEM_BYTES>>>(mask);
    // Output projection
    out_kernel<<<dim3(DD / 128, MM / 128), 256>>>(Wo, bo, out);
}

// round 15
// speedup vs baseline: 4.3896x; 1.5718x over previous
#include <cuda_runtime.h>
#include <cuda_fp16.h>
#include <cstdint>

// Problem constants
#define BB 2
#define SS 2048
#define DD 1024
#define HH 16
#define DKH 64
#define MM (BB * SS)   // 4096

// ------------------------------------------------------------------
// Scratch (device globals; no allocation allowed)
// ------------------------------------------------------------------
__device__ __align__(16) float g_Q[MM * DD];
__device__ __align__(16) float g_K[MM * DD];
__device__ __align__(16) float g_V[MM * DD];
__device__ __align__(16) float g_O[MM * DD];

// ------------------------------------------------------------------
// fp16 helpers
// ------------------------------------------------------------------
__device__ __forceinline__ uint32_t pack_h2(float lo, float hi) {
    __half2 h = __floats2half2_rn(lo, hi);   // lo -> low 16 bits
    return *(uint32_t*)&h;
}

__device__ __forceinline__ float ex2(float x) {
    float r;
    asm("ex2.approx.f32 %0, %1;" : "=f"(r) : "f"(x));
    return r;
}

__device__ __forceinline__ uint32_t smem_u32(const void* p) {
    uint32_t a;
    asm("{ .reg .u64 t; cvta.to.shared.u64 t, %1; cvt.u32.u64 %0, t; }" : "=r"(a) : "l"(p));
    return a;
}

// mma m16n8k16 fp16 inputs, fp32 accumulate
__device__ __forceinline__ void mma_f16(float* c, uint32_t a0, uint32_t a1,
                                        uint32_t a2, uint32_t a3,
                                        uint32_t b0, uint32_t b1) {
    asm volatile(
        "mma.sync.aligned.m16n8k16.row.col.f32.f16.f16.f32 "
        "{%0,%1,%2,%3}, {%4,%5,%6,%7}, {%8,%9}, {%0,%1,%2,%3};"
        : "+f"(c[0]), "+f"(c[1]), "+f"(c[2]), "+f"(c[3])
        : "r"(a0), "r"(a1), "r"(a2), "r"(a3), "r"(b0), "r"(b1));
}

// ==================================================================
// fp16 tensor-core GEMM: C[m,n] = sum_k A[m,k]*W[n,k] + bias[n]
// Block tile 128x128, K chunk 64 elem (32 half2 words). 8 warps 4(m)x2(n),
// each warp 32x64, 2x8 m16n8k16 fragments.
// ==================================================================
#define WP 36   // smem row pitch in 32-bit words (half2 pairs); conflict-free

__device__ __forceinline__ void gemm_mma(const float* __restrict__ A,
                                         const float* __restrict__ W,
                                         const float* __restrict__ bias,
                                         float* __restrict__ C,
                                         uint32_t* As, uint32_t* Bs)
{
    const int tid = threadIdx.x;
    const int wid = tid >> 5;
    const int lid = tid & 31;
    const int g   = lid >> 2;
    const int t   = lid & 3;
    const int wm  = (wid >> 1) * 32;
    const int wn  = (wid & 1) * 64;
    const int m0  = blockIdx.y * 128;
    const int n0  = blockIdx.x * 128;

    float acc[2][8][4];
#pragma unroll
    for (int i = 0; i < 2; i++)
#pragma unroll
        for (int j = 0; j < 8; j++)
#pragma unroll
            for (int r = 0; r < 4; r++) acc[i][j][r] = 0.f;

    for (int kt = 0; kt < DD; kt += 64) {
        __syncthreads();
        // Stage A[128][64] and B(=W)[128][64] as packed half2 words
#pragma unroll
        for (int i = 0; i < 8; i++) {
            int idx = tid + i * 256;           // 0..2047
            int row = idx >> 4;                // 0..127
            int q   = idx & 15;                // float4 index along k
            float4 av = *(const float4*)&A[(size_t)(m0 + row) * DD + kt + q * 4];
            uint2 aw = make_uint2(pack_h2(av.x, av.y), pack_h2(av.z, av.w));
            *(uint2*)&As[row * WP + q * 2] = aw;
            float4 wv = *(const float4*)&W[(size_t)(n0 + row) * DD + kt + q * 4];
            uint2 ww = make_uint2(pack_h2(wv.x, wv.y), pack_h2(wv.z, wv.w));
            *(uint2*)&Bs[row * WP + q * 2] = ww;
        }
        __syncthreads();

#pragma unroll
        for (int kc = 0; kc < 32; kc += 8) {   // 4 x k16 steps (8 words each)
            uint32_t a[2][4];
#pragma unroll
            for (int mt = 0; mt < 2; mt++) {
                const int ar = wm + mt * 16 + g;
                a[mt][0] = As[ar * WP + kc + t];
                a[mt][1] = As[(ar + 8) * WP + kc + t];
                a[mt][2] = As[ar * WP + kc + t + 4];
                a[mt][3] = As[(ar + 8) * WP + kc + t + 4];
            }
            uint32_t b[8][2];
#pragma unroll
            for (int nt = 0; nt < 8; nt++) {
                const int br = wn + nt * 8 + g;
                b[nt][0] = Bs[br * WP + kc + t];
                b[nt][1] = Bs[br * WP + kc + t + 4];
            }
#pragma unroll
            for (int mt = 0; mt < 2; mt++)
#pragma unroll
                for (int nt = 0; nt < 8; nt++)
                    mma_f16(acc[mt][nt], a[mt][0], a[mt][1], a[mt][2], a[mt][3],
                            b[nt][0], b[nt][1]);
        }
    }

    // Epilogue: c0/c1 -> (row g, cols 2t,2t+1); c2/c3 -> row g+8
#pragma unroll
    for (int mt = 0; mt < 2; mt++) {
        const int mrow0 = m0 + wm + mt * 16 + g;
#pragma unroll
        for (int nt = 0; nt < 8; nt++) {
            const int n = n0 + wn + nt * 8 + 2 * t;
            const float bx = bias[n], by = bias[n + 1];
            float2 lo = make_float2(acc[mt][nt][0] + bx, acc[mt][nt][1] + by);
            float2 hi = make_float2(acc[mt][nt][2] + bx, acc[mt][nt][3] + by);
            *(float2*)&C[(size_t)mrow0 * DD + n] = lo;
            *(float2*)&C[(size_t)(mrow0 + 8) * DD + n] = hi;
        }
    }
}

__global__ __launch_bounds__(256, 2)
void proj_kernel(const float* __restrict__ q_in, const float* __restrict__ k_in,
                 const float* __restrict__ v_in,
                 const float* __restrict__ Wq, const float* __restrict__ bq,
                 const float* __restrict__ Wk, const float* __restrict__ bk,
                 const float* __restrict__ Wv, const float* __restrict__ bv)
{
    __shared__ __align__(16) uint32_t As[128 * WP];
    __shared__ __align__(16) uint32_t Bs[128 * WP];
    const float* A; const float* W; const float* bias; float* C;
    if (blockIdx.z == 0)      { A = q_in; W = Wq; bias = bq; C = g_Q; }
    else if (blockIdx.z == 1) { A = k_in; W = Wk; bias = bk; C = g_K; }
    else                      { A = v_in; W = Wv; bias = bv; C = g_V; }
    gemm_mma(A, W, bias, C, As, Bs);
}

__global__ __launch_bounds__(256, 2)
void out_kernel(const float* __restrict__ Wo, const float* __restrict__ bo,
                float* __restrict__ out)
{
    __shared__ __align__(16) uint32_t As[128 * WP];
    __shared__ __align__(16) uint32_t Bs[128 * WP];
    gemm_mma(g_O, Wo, bo, out, As, Bs);
}

// ==================================================================
// fp16 tensor-core flash attention.
// Grid: (S/128, B*H). 8 warps; warp w owns q-rows w*16..w*16+15. Key tile 64.
// S C-fragments ARE the PV A-fragments (register pack identity, no P smem).
// V B-fragments loaded with ldmatrix.x2.trans from row-major Vs.
// ==================================================================
#define AP 36    // smem pitch in words; 144B rows (16B aligned for ldmatrix)

__global__ __launch_bounds__(256, 2)
void attn_tc_kernel(const int* __restrict__ mask)
{
    __shared__ __align__(16) uint32_t Qs[128 * AP];  // [q][d/2] half2, pre-scaled
    __shared__ __align__(16) uint32_t Ks[64 * AP];   // [key][d/2] half2
    __shared__ __align__(16) uint32_t Vs[64 * AP];   // [key][d/2] half2
    __shared__ int msk[64];

    const int tid = threadIdx.x;
    const int wid = tid >> 5, lid = tid & 31;
    const int g = lid >> 2, t = lid & 3;
    const int wq = wid * 16;
    const int q0 = blockIdx.x * 128;
    const int b  = blockIdx.y >> 4;
    const int h  = blockIdx.y & 15;
    const int hoff = h * DKH;
    const float* Qg = g_Q + (size_t)(b * SS) * DD + hoff;
    const float* Kg = g_K + (size_t)(b * SS) * DD + hoff;
    const float* Vg = g_V + (size_t)(b * SS) * DD + hoff;

    // scale * log2(e) folded into Q so softmax uses ex2 directly
    const float QSCALE = 0.125f * 1.4426950408889634f;

    // Stage Q tile once: 128 x 64 -> packed half2
#pragma unroll
    for (int i = 0; i < 8; i++) {
        int idx = tid + i * 256;
        int row = idx >> 4;
        int q   = idx & 15;
        float4 v = *(const float4*)&Qg[(size_t)(q0 + row) * DD + q * 4];
        uint2 w = make_uint2(pack_h2(v.x * QSCALE, v.y * QSCALE),
                             pack_h2(v.z * QSCALE, v.w * QSCALE));
        *(uint2*)&Qs[row * AP + q * 2] = w;
    }

    float m0 = -1e30f, m1 = -1e30f, l0 = 0.f, l1 = 0.f;
    float o[8][4];
#pragma unroll
    for (int nt = 0; nt < 8; nt++)
#pragma unroll
        for (int r = 0; r < 4; r++) o[nt][r] = 0.f;

    // per-lane ldmatrix row address base (lanes 0-15 used by x2)
    const uint32_t vrow_base = smem_u32(Vs) + (uint32_t)(lid & 15) * (AP * 4);

    for (int kb = 0; kb < SS; kb += 64) {
        __syncthreads();   // prev iter reads of Ks/Vs complete (mma.sync is sync)

        // Stage K and V tiles [64][64] as packed half2 (row-major)
#pragma unroll
        for (int i = 0; i < 4; i++) {
            int idx = tid + i * 256;
            int row = idx >> 4;
            int q   = idx & 15;
            float4 kv = *(const float4*)&Kg[(size_t)(kb + row) * DD + q * 4];
            uint2 kw = make_uint2(pack_h2(kv.x, kv.y), pack_h2(kv.z, kv.w));
            *(uint2*)&Ks[row * AP + q * 2] = kw;
            float4 vv = *(const float4*)&Vg[(size_t)(kb + row) * DD + q * 4];
            uint2 vw = make_uint2(pack_h2(vv.x, vv.y), pack_h2(vv.z, vv.w));
            *(uint2*)&Vs[row * AP + q * 2] = vw;
        }
        if (tid < 64) msk[tid] = mask[b * SS + kb + tid];
        __syncthreads();

        // ---- Scores: S = Q' @ K^T (already log2e*scale folded) ----
        float s[8][4];
#pragma unroll
        for (int nt = 0; nt < 8; nt++)
#pragma unroll
            for (int r = 0; r < 4; r++) s[nt][r] = 0.f;

#pragma unroll
        for (int kc = 0; kc < 32; kc += 8) {   // 4 x k16 steps over d=64
            uint32_t qa0 = Qs[(wq + g) * AP + kc + t];
            uint32_t qa1 = Qs[(wq + g + 8) * AP + kc + t];
            uint32_t qa2 = Qs[(wq + g) * AP + kc + t + 4];
            uint32_t qa3 = Qs[(wq + g + 8) * AP + kc + t + 4];
#pragma unroll
            for (int nt = 0; nt < 8; nt++) {
                uint32_t b0 = Ks[(nt * 8 + g) * AP + kc + t];
                uint32_t b1 = Ks[(nt * 8 + g) * AP + kc + t + 4];
                mma_f16(s[nt], qa0, qa1, qa2, qa3, b0, b1);
            }
        }

        // ---- Mask (all-ones in practice, honored anyway) ----
#pragma unroll
        for (int nt = 0; nt < 8; nt++) {
            const int c0 = nt * 8 + 2 * t;
            if (!msk[c0])     { s[nt][0] = -1e30f; s[nt][2] = -1e30f; }
            if (!msk[c0 + 1]) { s[nt][1] = -1e30f; s[nt][3] = -1e30f; }
        }

        // ---- Online softmax (rows g / g+8; quad reduction over t) ----
        float mx0 = -1e30f, mx1 = -1e30f;
#pragma unroll
        for (int nt = 0; nt < 8; nt++) {
            mx0 = fmaxf(mx0, fmaxf(s[nt][0], s[nt][1]));
            mx1 = fmaxf(mx1, fmaxf(s[nt][2], s[nt][3]));
        }
#pragma unroll
        for (int off = 1; off <= 2; off <<= 1) {
            mx0 = fmaxf(mx0, __shfl_xor_sync(0xffffffffu, mx0, off));
            mx1 = fmaxf(mx1, __shfl_xor_sync(0xffffffffu, mx1, off));
        }
        float mn0 = fmaxf(m0, mx0), mn1 = fmaxf(m1, mx1);
        float al0 = ex2(m0 - mn0), al1 = ex2(m1 - mn1);
        m0 = mn0; m1 = mn1;

        float sm0 = 0.f, sm1 = 0.f;
#pragma unroll
        for (int nt = 0; nt < 8; nt++) {
            s[nt][0] = ex2(s[nt][0] - mn0);
            s[nt][1] = ex2(s[nt][1] - mn0);
            s[nt][2] = ex2(s[nt][2] - mn1);
            s[nt][3] = ex2(s[nt][3] - mn1);
            sm0 += s[nt][0] + s[nt][1];
            sm1 += s[nt][2] + s[nt][3];
        }
#pragma unroll
        for (int off = 1; off <= 2; off <<= 1) {
            sm0 += __shfl_xor_sync(0xffffffffu, sm0, off);
            sm1 += __shfl_xor_sync(0xffffffffu, sm1, off);
        }
        l0 = l0 * al0 + sm0;
        l1 = l1 * al1 + sm1;
#pragma unroll
        for (int nt = 0; nt < 8; nt++) {
            o[nt][0] *= al0; o[nt][1] *= al0;
            o[nt][2] *= al1; o[nt][3] *= al1;
        }

        // ---- O += P @ V: S C-frags pack directly into PV A-frags ----
#pragma unroll
        for (int j = 0; j < 4; j++) {          // k16 chunks over 64 keys
            uint32_t a0 = pack_h2(s[2 * j][0],     s[2 * j][1]);
            uint32_t a1 = pack_h2(s[2 * j][2],     s[2 * j][3]);
            uint32_t a2 = pack_h2(s[2 * j + 1][0], s[2 * j + 1][1]);
            uint32_t a3 = pack_h2(s[2 * j + 1][2], s[2 * j + 1][3]);
            const uint32_t vaddr_j = vrow_base + (uint32_t)(j * 16 * AP * 4);
#pragma unroll
            for (int nt = 0; nt < 8; nt++) {
                uint32_t b0, b1;
                asm volatile(
                    "ldmatrix.sync.aligned.m8n8.x2.trans.shared.b16 {%0,%1}, [%2];"
                    : "=r"(b0), "=r"(b1) : "r"(vaddr_j + nt * 16));
                mma_f16(o[nt], a0, a1, a2, a3, b0, b1);
            }
        }
    }

    // ---- Normalize + write O tile ----
    const float inv0 = 1.0f / l0, inv1 = 1.0f / l1;
    float* Og = g_O + (size_t)(b * SS) * DD + hoff;
#pragma unroll
    for (int nt = 0; nt < 8; nt++) {
        const int d = nt * 8 + 2 * t;
        float2 lo = make_float2(o[nt][0] * inv0, o[nt][1] * inv0);
        float2 hi = make_float2(o[nt][2] * inv1, o[nt][3] * inv1);
        *(float2*)&Og[(size_t)(q0 + wq + g) * DD + d] = lo;
        *(float2*)&Og[(size_t)(q0 + wq + g + 8) * DD + d] = hi;
    }
}

// ------------------------------------------------------------------
// Launch
// ------------------------------------------------------------------
extern "C" void kernel_launch(void* const* d_in, const int* in_sizes, int n_in,
                              void* d_out, int out_size)
{
    const float* query = (const float*)d_in[0];
    const float* key   = (const float*)d_in[1];
    const float* value = (const float*)d_in[2];
    const int*   mask  = (const int*)  d_in[3];
    const float* Wq    = (const float*)d_in[4];
    const float* bq    = (const float*)d_in[5];
    const float* Wk    = (const float*)d_in[6];
    const float* bk    = (const float*)d_in[7];
    const float* Wv    = (const float*)d_in[8];
    const float* bv    = (const float*)d_in[9];
    const float* Wo    = (const float*)d_in[10];
    const float* bo    = (const float*)d_in[11];
    float* out = (float*)d_out;

    // QKV projections
    proj_kernel<<<dim3(DD / 128, MM / 128, 3), 256>>>(query, key, value,
                                                      Wq, bq, Wk, bk, Wv, bv);
    // fp16 tensor-core flash attention: (S/128 q-tiles, B*H)
    attn_tc_kernel<<<dim3(SS / 128, BB * HH), 256>>>(mask);
    // Output projection
    out_kernel<<<dim3(DD / 128, MM / 128), 256>>>(Wo, bo, out);
}

// round 16
// speedup vs baseline: 6.0985x; 1.3893x over previous
#include <cuda_runtime.h>
#include <cuda_fp16.h>
#include <cstdint>

// Problem constants
#define BB 2
#define SS 2048
#define DD 1024
#define DW 512          // words (half2) per row
#define HH 16
#define DKH 64
#define MM (BB * SS)    // 4096

// ------------------------------------------------------------------
// Scratch (device globals; no allocation allowed) — all packed half2
// ------------------------------------------------------------------
__device__ __align__(16) uint32_t g_Qi[MM * DW];   // fp16 inputs
__device__ __align__(16) uint32_t g_Ki[MM * DW];
__device__ __align__(16) uint32_t g_Vi[MM * DW];
__device__ __align__(16) uint32_t g_Wq16[DD * DW]; // fp16 weights
__device__ __align__(16) uint32_t g_Wk16[DD * DW];
__device__ __align__(16) uint32_t g_Wv16[DD * DW];
__device__ __align__(16) uint32_t g_Wo16[DD * DW];
__device__ __align__(16) uint32_t g_Qh[MM * DW];   // projected Q/K/V (fp16)
__device__ __align__(16) uint32_t g_Kh[MM * DW];
__device__ __align__(16) uint32_t g_Vh[MM * DW];
__device__ __align__(16) uint32_t g_Oh[MM * DW];   // attention out (fp16)

// ------------------------------------------------------------------
// helpers
// ------------------------------------------------------------------
__device__ __forceinline__ uint32_t pack_h2(float lo, float hi) {
    __half2 h = __floats2half2_rn(lo, hi);
    return *(uint32_t*)&h;
}
__device__ __forceinline__ float ex2(float x) {
    float r; asm("ex2.approx.f32 %0, %1;" : "=f"(r) : "f"(x)); return r;
}
__device__ __forceinline__ uint32_t smem_u32(const void* p) {
    uint32_t a;
    asm("{ .reg .u64 t; cvta.to.shared.u64 t, %1; cvt.u32.u64 %0, t; }" : "=r"(a) : "l"(p));
    return a;
}
__device__ __forceinline__ void cpa16(uint32_t saddr, const void* g) {
    asm volatile("cp.async.cg.shared.global [%0], [%1], 16;" :: "r"(saddr), "l"(g) : "memory");
}
#define CP_COMMIT() asm volatile("cp.async.commit_group;" ::: "memory")
#define CP_WAIT0()  asm volatile("cp.async.wait_group 0;" ::: "memory")
#define CP_WAIT1()  asm volatile("cp.async.wait_group 1;" ::: "memory")

__device__ __forceinline__ void mma_f16(float* c, uint32_t a0, uint32_t a1,
                                        uint32_t a2, uint32_t a3,
                                        uint32_t b0, uint32_t b1) {
    asm volatile(
        "mma.sync.aligned.m16n8k16.row.col.f32.f16.f16.f32 "
        "{%0,%1,%2,%3}, {%4,%5,%6,%7}, {%8,%9}, {%0,%1,%2,%3};"
        : "+f"(c[0]), "+f"(c[1]), "+f"(c[2]), "+f"(c[3])
        : "r"(a0), "r"(a1), "r"(a2), "r"(a3), "r"(b0), "r"(b1));
}

// ------------------------------------------------------------------
// fp32 -> packed fp16 conversion pre-pass
// ------------------------------------------------------------------
__global__ void cvt_kernel(const float4* __restrict__ src, uint2* __restrict__ dst,
                           int n4)
{
    int i = blockIdx.x * blockDim.x + threadIdx.x;
    if (i < n4) {
        float4 v = src[i];
        dst[i] = make_uint2(pack_h2(v.x, v.y), pack_h2(v.z, v.w));
    }
}

// ==================================================================
// fp16 GEMM, cp.async double-buffered: C = A @ W^T + bias
// Block 128x128, K chunk 64 halves (32 words). 8 warps 4(m)x2(n).
// smem word layout: Abuf0 @0, Abuf1 @4608, Bbuf0 @9216, Bbuf1 @13824
// pitch 36 words/row (144B, 16B-aligned, fragment-conflict-free).
// ==================================================================
#define WP 36
#define GEMM_SMEM_BYTES (18432 * 4)

__device__ __forceinline__ void gemm_issue(const uint32_t* __restrict__ Ah,
                                           const uint32_t* __restrict__ Wh,
                                           int m0, int n0, int kw,   // kw = k offset in words
                                           uint32_t sA, uint32_t sB, int tid)
{
#pragma unroll
    for (int i = 0; i < 4; i++) {
        int idx = tid + i * 256;       // 0..1023
        int row = idx >> 3;            // 0..127
        int c   = idx & 7;             // 16B chunk
        cpa16(sA + row * 144 + c * 16, &Ah[(size_t)(m0 + row) * DW + kw + c * 4]);
        cpa16(sB + row * 144 + c * 16, &Wh[(size_t)(n0 + row) * DW + kw + c * 4]);
    }
}

template <bool HALF_OUT>
__device__ __forceinline__ void gemm_body(const uint32_t* __restrict__ Ah,
                                          const uint32_t* __restrict__ Wh,
                                          const float* __restrict__ bias,
                                          void* __restrict__ Cp,
                                          uint32_t* sw)
{
    const uint32_t sbase = smem_u32(sw);
    const int tid = threadIdx.x;
    const int wid = tid >> 5, lid = tid & 31;
    const int g = lid >> 2, t = lid & 3;
    const int wm = (wid >> 1) * 32;
    const int wn = (wid & 1) * 64;
    const int m0 = blockIdx.y * 128;
    const int n0 = blockIdx.x * 128;

    float acc[2][8][4];
#pragma unroll
    for (int i = 0; i < 2; i++)
#pragma unroll
        for (int j = 0; j < 8; j++)
#pragma unroll
            for (int r = 0; r < 4; r++) acc[i][j][r] = 0.f;

    // preload chunk 0 -> buffer 0
    gemm_issue(Ah, Wh, m0, n0, 0, sbase, sbase + 9216 * 4, tid);
    CP_COMMIT();

    for (int ch = 0; ch < 16; ch++) {
        const int p = ch & 1;
        if (ch + 1 < 16) {
            gemm_issue(Ah, Wh, m0, n0, (ch + 1) * 32,
                       sbase + (1 - p) * 4608 * 4,
                       sbase + (9216 + (1 - p) * 4608) * 4, tid);
            CP_COMMIT();
            CP_WAIT1();
        } else {
            CP_WAIT0();
        }
        __syncthreads();

        const uint32_t* As = sw + p * 4608;
        const uint32_t* Bs = sw + 9216 + p * 4608;
#pragma unroll
        for (int kc = 0; kc < 32; kc += 8) {
            uint32_t a[2][4];
#pragma unroll
            for (int mt = 0; mt < 2; mt++) {
                const int ar = wm + mt * 16 + g;
                a[mt][0] = As[ar * WP + kc + t];
                a[mt][1] = As[(ar + 8) * WP + kc + t];
                a[mt][2] = As[ar * WP + kc + t + 4];
                a[mt][3] = As[(ar + 8) * WP + kc + t + 4];
            }
            uint32_t b[8][2];
#pragma unroll
            for (int nt = 0; nt < 8; nt++) {
                const int br = wn + nt * 8 + g;
                b[nt][0] = Bs[br * WP + kc + t];
                b[nt][1] = Bs[br * WP + kc + t + 4];
            }
#pragma unroll
            for (int mt = 0; mt < 2; mt++)
#pragma unroll
                for (int nt = 0; nt < 8; nt++)
                    mma_f16(acc[mt][nt], a[mt][0], a[mt][1], a[mt][2], a[mt][3],
                            b[nt][0], b[nt][1]);
        }
        __syncthreads();
    }

    // Epilogue
#pragma unroll
    for (int mt = 0; mt < 2; mt++) {
        const int mrow0 = m0 + wm + mt * 16 + g;
#pragma unroll
        for (int nt = 0; nt < 8; nt++) {
            const int n = n0 + wn + nt * 8 + 2 * t;
            const float bx = bias[n], by = bias[n + 1];
            if (HALF_OUT) {
                uint32_t* C16 = (uint32_t*)Cp;
                C16[((size_t)mrow0 * DD + n) >> 1] =
                    pack_h2(acc[mt][nt][0] + bx, acc[mt][nt][1] + by);
                C16[((size_t)(mrow0 + 8) * DD + n) >> 1] =
                    pack_h2(acc[mt][nt][2] + bx, acc[mt][nt][3] + by);
            } else {
                float* Cf = (float*)Cp;
                float2 lo = make_float2(acc[mt][nt][0] + bx, acc[mt][nt][1] + by);
                float2 hi = make_float2(acc[mt][nt][2] + bx, acc[mt][nt][3] + by);
                *(float2*)&Cf[(size_t)mrow0 * DD + n] = lo;
                *(float2*)&Cf[(size_t)(mrow0 + 8) * DD + n] = hi;
            }
        }
    }
}

__global__ __launch_bounds__(256, 2)
void proj_kernel(const float* __restrict__ bq, const float* __restrict__ bk,
                 const float* __restrict__ bv)
{
    extern __shared__ __align__(16) uint32_t sw[];
    const uint32_t* A; const uint32_t* W; const float* bias; uint32_t* C;
    if (blockIdx.z == 0)      { A = g_Qi; W = g_Wq16; bias = bq; C = g_Qh; }
    else if (blockIdx.z == 1) { A = g_Ki; W = g_Wk16; bias = bk; C = g_Kh; }
    else                      { A = g_Vi; W = g_Wv16; bias = bv; C = g_Vh; }
    gemm_body<true>(A, W, bias, C, sw);
}

__global__ __launch_bounds__(256, 2)
void out_kernel(const float* __restrict__ bo, float* __restrict__ out)
{
    extern __shared__ __align__(16) uint32_t sw[];
    gemm_body<false>(g_Oh, g_Wo16, bo, out, sw);
}

// ==================================================================
// fp16 flash attention, cp.async double-buffered K/V.
// Grid: (S/128, B*H). 8 warps; warp w owns q-rows w*16..w*16+15. Key tile 64.
// smem word layout: Q @0 (128x36), K0 @4608, K1 @6912, V0 @9216, V1 @11520,
//                   msk0 @13824, msk1 @13888. Total 13952 words.
// ==================================================================
#define AP 36
#define AW_K0 4608
#define AW_V0 9216
#define AW_M0 13824
#define ATTN_SMEM_BYTES (13952 * 4)

__device__ __forceinline__ void attn_issue_kv(const uint32_t* __restrict__ Kg,
                                              const uint32_t* __restrict__ Vg,
                                              const int* __restrict__ maskp,
                                              int kb, int buf, uint32_t sbase, int tid)
{
    const uint32_t sK = sbase + (AW_K0 + buf * 2304) * 4;
    const uint32_t sV = sbase + (AW_V0 + buf * 2304) * 4;
#pragma unroll
    for (int i = 0; i < 2; i++) {
        int idx = tid + i * 256;       // 0..511
        int row = idx >> 3;            // 0..63
        int c   = idx & 7;
        cpa16(sK + row * 144 + c * 16, &Kg[(size_t)(kb + row) * DW + c * 4]);
        cpa16(sV + row * 144 + c * 16, &Vg[(size_t)(kb + row) * DW + c * 4]);
    }
    if (tid < 16)
        cpa16(sbase + (AW_M0 + buf * 64) * 4 + tid * 16, &maskp[kb + tid * 4]);
}

__global__ __launch_bounds__(256, 2)
void attn_tc_kernel(const int* __restrict__ mask)
{
    extern __shared__ __align__(16) uint32_t sw[];
    const uint32_t sbase = smem_u32(sw);

    const int tid = threadIdx.x;
    const int wid = tid >> 5, lid = tid & 31;
    const int g = lid >> 2, t = lid & 3;
    const int wq = wid * 16;
    const int q0 = blockIdx.x * 128;
    const int b  = blockIdx.y >> 4;
    const int h  = blockIdx.y & 15;
    const uint32_t* Qg = g_Qh + (size_t)(b * SS) * DW + h * 32;
    const uint32_t* Kg = g_Kh + (size_t)(b * SS) * DW + h * 32;
    const uint32_t* Vg = g_Vh + (size_t)(b * SS) * DW + h * 32;
    const int* maskp = mask + b * SS;

    // softmax scale (1/8) * log2(e), applied to scores post-MMA
    const float SC = 0.125f * 1.4426950408889634f;

    // Stage Q tile (cp.async) + first K/V tile + mask -> group 0
#pragma unroll
    for (int i = 0; i < 4; i++) {
        int idx = tid + i * 256;
        int row = idx >> 3;
        int c   = idx & 7;
        cpa16(sbase + (row * AP + c * 4) * 4, &Qg[(size_t)(q0 + row) * DW + c * 4]);
    }
    attn_issue_kv(Kg, Vg, maskp, 0, 0, sbase, tid);
    CP_COMMIT();

    float m0 = -1e30f, m1 = -1e30f, l0 = 0.f, l1 = 0.f;
    float o[8][4];
#pragma unroll
    for (int nt = 0; nt < 8; nt++)
#pragma unroll
        for (int r = 0; r < 4; r++) o[nt][r] = 0.f;

    for (int ti = 0; ti < SS / 64; ti++) {
        const int p = ti & 1;
        if (ti + 1 < SS / 64) {
            attn_issue_kv(Kg, Vg, maskp, (ti + 1) * 64, 1 - p, sbase, tid);
            CP_COMMIT();
            CP_WAIT1();
        } else {
            CP_WAIT0();
        }
        __syncthreads();

        const uint32_t* Qs = sw;
        const uint32_t* Ks = sw + AW_K0 + p * 2304;
        const int* msk = (const int*)(sw + AW_M0 + p * 64);
        const uint32_t vrow_base = sbase + (AW_V0 + p * 2304) * 4
                                 + (uint32_t)(lid & 15) * 144;

        // ---- Scores: S = Q @ K^T ----
        float s[8][4];
#pragma unroll
        for (int nt = 0; nt < 8; nt++)
#pragma unroll
            for (int r = 0; r < 4; r++) s[nt][r] = 0.f;

#pragma unroll
        for (int kc = 0; kc < 32; kc += 8) {
            uint32_t qa0 = Qs[(wq + g) * AP + kc + t];
            uint32_t qa1 = Qs[(wq + g + 8) * AP + kc + t];
            uint32_t qa2 = Qs[(wq + g) * AP + kc + t + 4];
            uint32_t qa3 = Qs[(wq + g + 8) * AP + kc + t + 4];
#pragma unroll
            for (int nt = 0; nt < 8; nt++) {
                uint32_t b0 = Ks[(nt * 8 + g) * AP + kc + t];
                uint32_t b1 = Ks[(nt * 8 + g) * AP + kc + t + 4];
                mma_f16(s[nt], qa0, qa1, qa2, qa3, b0, b1);
            }
        }

        // ---- Scale + mask ----
#pragma unroll
        for (int nt = 0; nt < 8; nt++) {
            const int c0 = nt * 8 + 2 * t;
            const int mk0 = msk[c0], mk1 = msk[c0 + 1];
            s[nt][0] = mk0 ? s[nt][0] * SC : -1e30f;
            s[nt][1] = mk1 ? s[nt][1] * SC : -1e30f;
            s[nt][2] = mk0 ? s[nt][2] * SC : -1e30f;
            s[nt][3] = mk1 ? s[nt][3] * SC : -1e30f;
        }

        // ---- Online softmax (rows g / g+8; quad reduction over t) ----
        float mx0 = -1e30f, mx1 = -1e30f;
#pragma unroll
        for (int nt = 0; nt < 8; nt++) {
            mx0 = fmaxf(mx0, fmaxf(s[nt][0], s[nt][1]));
            mx1 = fmaxf(mx1, fmaxf(s[nt][2], s[nt][3]));
        }
#pragma unroll
        for (int off = 1; off <= 2; off <<= 1) {
            mx0 = fmaxf(mx0, __shfl_xor_sync(0xffffffffu, mx0, off));
            mx1 = fmaxf(mx1, __shfl_xor_sync(0xffffffffu, mx1, off));
        }
        float mn0 = fmaxf(m0, mx0), mn1 = fmaxf(m1, mx1);
        float al0 = ex2(m0 - mn0), al1 = ex2(m1 - mn1);
        m0 = mn0; m1 = mn1;

        float sm0 = 0.f, sm1 = 0.f;
#pragma unroll
        for (int nt = 0; nt < 8; nt++) {
            s[nt][0] = ex2(s[nt][0] - mn0);
            s[nt][1] = ex2(s[nt][1] - mn0);
            s[nt][2] = ex2(s[nt][2] - mn1);
            s[nt][3] = ex2(s[nt][3] - mn1);
            sm0 += s[nt][0] + s[nt][1];
            sm1 += s[nt][2] + s[nt][3];
        }
#pragma unroll
        for (int off = 1; off <= 2; off <<= 1) {
            sm0 += __shfl_xor_sync(0xffffffffu, sm0, off);
            sm1 += __shfl_xor_sync(0xffffffffu, sm1, off);
        }
        l0 = l0 * al0 + sm0;
        l1 = l1 * al1 + sm1;
#pragma unroll
        for (int nt = 0; nt < 8; nt++) {
            o[nt][0] *= al0; o[nt][1] *= al0;
            o[nt][2] *= al1; o[nt][3] *= al1;
        }

        // ---- O += P @ V (S frags pack to A frags; V via ldmatrix.trans) ----
#pragma unroll
        for (int j = 0; j < 4; j++) {
            uint32_t a0 = pack_h2(s[2 * j][0],     s[2 * j][1]);
            uint32_t a1 = pack_h2(s[2 * j][2],     s[2 * j][3]);
            uint32_t a2 = pack_h2(s[2 * j + 1][0], s[2 * j + 1][1]);
            uint32_t a3 = pack_h2(s[2 * j + 1][2], s[2 * j + 1][3]);
            const uint32_t vaddr_j = vrow_base + (uint32_t)(j * 16 * AP * 4);
#pragma unroll
            for (int nt = 0; nt < 8; nt++) {
                uint32_t b0, b1;
                asm volatile(
                    "ldmatrix.sync.aligned.m8n8.x2.trans.shared.b16 {%0,%1}, [%2];"
                    : "=r"(b0), "=r"(b1) : "r"(vaddr_j + nt * 16));
                mma_f16(o[nt], a0, a1, a2, a3, b0, b1);
            }
        }
        __syncthreads();
    }

    // ---- Normalize + write O tile (fp16 packed) ----
    const float inv0 = 1.0f / l0, inv1 = 1.0f / l1;
    uint32_t* Og = g_Oh + (size_t)(b * SS) * DW + h * 32;
#pragma unroll
    for (int nt = 0; nt < 8; nt++) {
        const int dw = nt * 4 + t;   // word offset within head (d = nt*8+2t)
        Og[(size_t)(q0 + wq + g) * DW + dw] =
            pack_h2(o[nt][0] * inv0, o[nt][1] * inv0);
        Og[(size_t)(q0 + wq + g + 8) * DW + dw] =
            pack_h2(o[nt][2] * inv1, o[nt][3] * inv1);
    }
}

// ------------------------------------------------------------------
// Launch
// ------------------------------------------------------------------
extern "C" void kernel_launch(void* const* d_in, const int* in_sizes, int n_in,
                              void* d_out, int out_size)
{
    const float* query = (const float*)d_in[0];
    const float* key   = (const float*)d_in[1];
    const float* value = (const float*)d_in[2];
    const int*   mask  = (const int*)  d_in[3];
    const float* Wq    = (const float*)d_in[4];
    const float* bq    = (const float*)d_in[5];
    const float* Wk    = (const float*)d_in[6];
    const float* bk    = (const float*)d_in[7];
    const float* Wv    = (const float*)d_in[8];
    const float* bv    = (const float*)d_in[9];
    const float* Wo    = (const float*)d_in[10];
    const float* bo    = (const float*)d_in[11];
    float* out = (float*)d_out;

    cudaFuncSetAttribute(proj_kernel, cudaFuncAttributeMaxDynamicSharedMemorySize,
                         GEMM_SMEM_BYTES);
    cudaFuncSetAttribute(out_kernel, cudaFuncAttributeMaxDynamicSharedMemorySize,
                         GEMM_SMEM_BYTES);
    cudaFuncSetAttribute(attn_tc_kernel, cudaFuncAttributeMaxDynamicSharedMemorySize,
                         ATTN_SMEM_BYTES);

    // Resolve device-global addresses (host-side; no allocation)
    uint32_t *qi, *ki, *vi, *wq16, *wk16, *wv16, *wo16;
    cudaGetSymbolAddress((void**)&qi, g_Qi);
    cudaGetSymbolAddress((void**)&ki, g_Ki);
    cudaGetSymbolAddress((void**)&vi, g_Vi);
    cudaGetSymbolAddress((void**)&wq16, g_Wq16);
    cudaGetSymbolAddress((void**)&wk16, g_Wk16);
    cudaGetSymbolAddress((void**)&wv16, g_Wv16);
    cudaGetSymbolAddress((void**)&wo16, g_Wo16);

    const int n4_in = MM * DD / 4;   // 1048576
    const int n4_w  = DD * DD / 4;   // 262144

    // fp32 -> fp16 pre-pass
    cvt_kernel<<<n4_in / 256, 256>>>((const float4*)query, (uint2*)qi, n4_in);
    cvt_kernel<<<n4_in / 256, 256>>>((const float4*)key,   (uint2*)ki, n4_in);
    cvt_kernel<<<n4_in / 256, 256>>>((const float4*)value, (uint2*)vi, n4_in);
    cvt_kernel<<<n4_w / 256, 256>>>((const float4*)Wq, (uint2*)wq16, n4_w);
    cvt_kernel<<<n4_w / 256, 256>>>((const float4*)Wk, (uint2*)wk16, n4_w);
    cvt_kernel<<<n4_w / 256, 256>>>((const float4*)Wv, (uint2*)wv16, n4_w);
    cvt_kernel<<<n4_w / 256, 256>>>((const float4*)Wo, (uint2*)wo16, n4_w);

    // QKV projections
    proj_kernel<<<dim3(DD / 128, MM / 128, 3), 256, GEMM_SMEM_BYTES>>>(bq, bk, bv);
    // fp16 flash attention: (S/128 q-tiles, B*H)
    attn_tc_kernel<<<dim3(SS / 128, BB * HH), 256, ATTN_SMEM_BYTES>>>(mask);
    // Output projection
    out_kernel<<<dim3(DD / 128, MM / 128), 256, GEMM_SMEM_BYTES>>>(bo, out);
}